// round 12
// baseline (speedup 1.0000x reference)
#include <cuda_runtime.h>
#include <cuda_fp16.h>
#include <cstdint>

// ---------------------------------------------------------------------------
// LaneATT — fp16 mma.sync m16n8k16, 128x256 blocks (warp 64x64), BK=64,
// 4-stage cp.async ring, fp16 scores, fused gather+transpose.
//   B=32, A=1000 (pad 1024), CH=768, NSC=999 (pad 1024)
//   1) gather index; W^T -> fp16 [n][k]; padded fp32 bias
//   2) fused gather: feats fp16 [b][1024][768] AND featsT fp16 [b][768][1024]
//   3) GEMM1: scores(fp16, stride 1024) = feats @ W + b  (32768 x 1024, K=768)
//   4) softmax(999) -> attn fp16 [b][1024][1024], eye-shift
//   5) GEMM2: out[b] = attn[b] @ feats[b]                (1024 x 768, K=1024)
// ---------------------------------------------------------------------------

static constexpr int Bn  = 32;
static constexpr int An  = 1000;
static constexpr int APAD = 1024;
static constexpr int Cn  = 64;
static constexpr int Hn  = 12;
static constexpr int Wn  = 20;
static constexpr int CHn = Cn * Hn;        // 768
static constexpr int NSC = An - 1;         // 999
static constexpr int NPAD = 1024;
static constexpr int FVB = Cn * Hn * Wn;   // 15360
static constexpr int MtotPad = Bn * APAD;  // 32768

__device__ __half g_featsH[Bn * APAD * CHn];       // 48 MB  [b][a][ch]
__device__ __half g_featsTH[Bn * CHn * APAD];      // 48 MB  [b][ch][a]
__device__ __half g_attnH[Bn * APAD * NPAD];       // 64 MB  [b][i][j]
__device__ __half g_scoresH[(long)MtotPad * NPAD]; // 64 MB  padded stride
__device__ __half g_WTH[APAD * CHn];               // 1.5 MB [n][k]
__device__ float  g_biasPad[NPAD];
__device__ int    g_comb[An * CHn];

// ---------------------------------------------------------------------------
__device__ __forceinline__ uint32_t smem_u32(const void* p) {
    return (uint32_t)__cvta_generic_to_shared(p);
}
__device__ __forceinline__ void cpa16(uint32_t dst, const void* src) {
    asm volatile("cp.async.cg.shared.global [%0], [%1], 16;\n" :: "r"(dst), "l"(src));
}
#define CP_COMMIT() asm volatile("cp.async.commit_group;\n" ::: "memory")
#define CP_WAIT2()  asm volatile("cp.async.wait_group 2;\n" ::: "memory")
#define CP_WAIT1()  asm volatile("cp.async.wait_group 1;\n" ::: "memory")
#define CP_WAIT0()  asm volatile("cp.async.wait_group 0;\n" ::: "memory")

__device__ __forceinline__ void ldsm_x4(uint32_t* r, uint32_t addr) {
    asm volatile("ldmatrix.sync.aligned.m8n8.x4.shared.b16 {%0,%1,%2,%3}, [%4];"
                 : "=r"(r[0]), "=r"(r[1]), "=r"(r[2]), "=r"(r[3]) : "r"(addr));
}
__device__ __forceinline__ void ldsm_x2(uint32_t* r, uint32_t addr) {
    asm volatile("ldmatrix.sync.aligned.m8n8.x2.shared.b16 {%0,%1}, [%2];"
                 : "=r"(r[0]), "=r"(r[1]) : "r"(addr));
}
__device__ __forceinline__ void mma16(float* c, const uint32_t* a, const uint32_t* b) {
    asm volatile(
        "mma.sync.aligned.m16n8k16.row.col.f32.f16.f16.f32 "
        "{%0,%1,%2,%3}, {%4,%5,%6,%7}, {%8,%9}, {%0,%1,%2,%3};\n"
        : "+f"(c[0]), "+f"(c[1]), "+f"(c[2]), "+f"(c[3])
        : "r"(a[0]), "r"(a[1]), "r"(a[2]), "r"(a[3]), "r"(b[0]), "r"(b[1]));
}

// ---------------------------------------------------------------------------
// prep kernels
// ---------------------------------------------------------------------------
__global__ void k_precomp(const int* __restrict__ z, const int* __restrict__ y,
                          const int* __restrict__ x, const int* __restrict__ inv) {
    int i = blockIdx.x * blockDim.x + threadIdx.x;
    if (i >= An * CHn) return;
    g_comb[i] = inv[i] ? -1 : (z[i] * (Hn * Wn) + y[i] * Wn + x[i]);
}

__global__ void k_WT(const float* __restrict__ Wt, const float* __restrict__ bias) {
    int i = blockIdx.x * blockDim.x + threadIdx.x;
    if (i >= APAD * CHn) return;
    int n = i / CHn, k = i - n * CHn;
    g_WTH[i] = (n < NSC) ? __float2half(__ldg(Wt + (long)k * NSC + n)) : __half(0.0f);
    if (i < NPAD) g_biasPad[i] = (i < NSC) ? __ldg(bias + i) : 0.0f;
}

// fused gather + transpose: one block per (32-anchor tile, batch).
// smem tile t[32][TS] (TS=770: stride/2 mod 32 == 1 -> conflict-free T reads)
static constexpr int TS = 770;
static constexpr int GT_SMEM = 32 * TS * 2;   // 49280 B (dynamic)

__global__ __launch_bounds__(256) void k_gatherT(const float* __restrict__ fv) {
    extern __shared__ __half t[];
    const int a0 = blockIdx.x * 32;
    const int b  = blockIdx.y;
    const float* fvb = fv + b * FVB;
    const int tid = threadIdx.x;

    // gather phase: thread -> anchor a0 + (tid/8), channels (tid%8) + 8j
    {
        int al = tid >> 3;
        int c0 = tid & 7;
        int a  = a0 + al;
        const int* cmb = g_comb + (long)a * CHn;   // only read if a < An
        bool valid = (a < An);
#pragma unroll 4
        for (int j = 0; j < 96; j++) {
            int ch = c0 + 8 * j;
            float v = 0.0f;
            if (valid) {
                int ix = cmb[ch];
                if (ix >= 0) v = __ldg(fvb + ix);
            }
            t[al * TS + ch] = __float2half(v);
        }
    }
    __syncthreads();

    // featsH write: rows a0..a0+31, 384 half2 per row
    {
        __half2* out = reinterpret_cast<__half2*>(
            g_featsH + ((long)b * APAD + a0) * CHn);
        for (int idx = tid; idx < 32 * 384; idx += 256) {
            int al = idx / 384, p = idx - al * 384;
            __half2 h = __halves2half2(t[al * TS + 2 * p], t[al * TS + 2 * p + 1]);
            out[al * 384 + p] = h;
        }
    }
    // featsT write: 768 ch rows x 16 half2 (column a0..a0+31)
    {
        for (int idx = tid; idx < 768 * 16; idx += 256) {
            int ch = idx >> 4, p = idx & 15;
            __half2 h = __halves2half2(t[(2 * p) * TS + ch], t[(2 * p + 1) * TS + ch]);
            *reinterpret_cast<__half2*>(
                g_featsTH + ((long)b * CHn + ch) * APAD + a0 + 2 * p) = h;
        }
    }
}

// ---------------------------------------------------------------------------
// GEMM: D[128 x 256] = A[128 x K] @ B[256 rows x K]^T (both K-major), fp16 in,
// fp32 accum. 8 warps (2x4), warp tile 64x64, BK=64, 4-stage cp.async ring.
//  G1: A=featsH  lda=768,  B=WTH     ldb=768,  K=768  -> scoresH(+bias) fp16
//  G2: A=attnH   lda=1024, B=featsTH ldb=1024, K=1024 -> out fp32 (row guard)
// ---------------------------------------------------------------------------
static constexpr int ROWB = 144;                 // smem row: 128B data + 16 pad
static constexpr int A_TB = 128 * ROWB;          // 18432
static constexpr int B_TB = 256 * ROWB;          // 36864
static constexpr int STG  = A_TB + B_TB;         // 55296
static constexpr int SMEM_G = 4 * STG;           // 221184

template <bool G1>
__global__ __launch_bounds__(256, 1) void k_gemm(float* __restrict__ out) {
    constexpr int NS = G1 ? (CHn / 64) : (APAD / 64);   // 12 / 16

    extern __shared__ char smem[];
    uint32_t sb = smem_u32(smem);

    const int tid = threadIdx.x;
    const int warp = tid >> 5, lane = tid & 31;
    const int wm = warp >> 2, wn = warp & 3;     // 2 x 4 warps -> 64x64 tiles
    const int m0 = blockIdx.y * 128;
    const int n0 = blockIdx.x * 256;

    const __half* Ag;
    const __half* Bg;
    long lda, ldb;
    if (G1) { Ag = g_featsH; Bg = g_WTH; lda = CHn; ldb = CHn; }
    else {
        int b = blockIdx.z;
        Ag = g_attnH + (long)b * APAD * NPAD;
        Bg = g_featsTH + (long)b * CHn * APAD;
        lda = NPAD; ldb = APAD;
    }

    auto load_stage = [&](int s, int buf) {
        int k0 = s * 64;
        uint32_t ab = sb + buf * STG;
        uint32_t bb = ab + A_TB;
#pragma unroll
        for (int i = 0; i < 4; i++) {            // A: 1024 cp.async
            int idx = tid + i * 256;
            int row = idx >> 3, ch = idx & 7;
            cpa16(ab + row * ROWB + ch * 16,
                  Ag + (long)(m0 + row) * lda + k0 + ch * 8);
        }
#pragma unroll
        for (int i = 0; i < 8; i++) {            // B: 2048 cp.async
            int idx = tid + i * 256;
            int row = idx >> 3, ch = idx & 7;
            cpa16(bb + row * ROWB + ch * 16,
                  Bg + (long)(n0 + row) * ldb + k0 + ch * 8);
        }
    };

    float acc[4][8][4];
#pragma unroll
    for (int i = 0; i < 4; i++)
#pragma unroll
        for (int j = 0; j < 8; j++)
#pragma unroll
            for (int v = 0; v < 4; v++) acc[i][j][v] = 0.0f;

    load_stage(0, 0); CP_COMMIT();
    load_stage(1, 1); CP_COMMIT();
    load_stage(2, 2); CP_COMMIT();

    const int l15 = lane & 15;
    const int ahi = (lane >> 4) << 4;        // +16B: k upper half for lanes 16-31
    const int bhi = ((lane >> 3) & 1) << 4;  // +16B: k upper 8 for lanes 8-15

    for (int s = 0; s < NS; s++) {
        if (s + 2 < NS) CP_WAIT2();
        else if (s + 1 < NS) CP_WAIT1();
        else CP_WAIT0();
        __syncthreads();

        uint32_t ab = sb + (s & 3) * STG;
        uint32_t bb = ab + A_TB;
#pragma unroll
        for (int kk = 0; kk < 4; kk++) {
            uint32_t af[4][4], bf[8][2];
#pragma unroll
            for (int mt = 0; mt < 4; mt++) {
                int row = wm * 64 + mt * 16 + l15;
                ldsm_x4(af[mt], ab + row * ROWB + kk * 32 + ahi);
            }
#pragma unroll
            for (int nt = 0; nt < 8; nt++) {
                int nr = wn * 64 + nt * 8 + (l15 & 7);
                ldsm_x2(bf[nt], bb + nr * ROWB + kk * 32 + bhi);
            }
#pragma unroll
            for (int mt = 0; mt < 4; mt++)
#pragma unroll
                for (int nt = 0; nt < 8; nt++)
                    mma16(acc[mt][nt], af[mt], bf[nt]);
        }

        if (s + 3 < NS) { load_stage(s + 3, (s + 3) & 3); CP_COMMIT(); }
    }

    // epilogue: c{0,1} -> (row g, cols 2t,2t+1); c{2,3} -> row g+8
    const int g = lane >> 2, t4 = lane & 3;
#pragma unroll
    for (int mt = 0; mt < 4; mt++) {
#pragma unroll
        for (int nt = 0; nt < 8; nt++) {
            int row = m0 + wm * 64 + mt * 16 + g;
            int col = n0 + wn * 64 + nt * 8 + t4 * 2;
            if (G1) {
                float2 bv = *reinterpret_cast<const float2*>(g_biasPad + col);
#pragma unroll
                for (int h = 0; h < 2; h++) {
                    __half2 hv = __floats2half2_rn(acc[mt][nt][h * 2] + bv.x,
                                                   acc[mt][nt][h * 2 + 1] + bv.y);
                    *reinterpret_cast<__half2*>(
                        g_scoresH + (long)(row + h * 8) * NPAD + col) = hv;
                }
            } else {
#pragma unroll
                for (int h = 0; h < 2; h++) {
                    int r = row + h * 8;
                    if (r < An) {
                        float2 v = make_float2(acc[mt][nt][h * 2], acc[mt][nt][h * 2 + 1]);
                        *reinterpret_cast<float2*>(
                            out + ((long)blockIdx.z * An + r) * CHn + col) = v;
                    }
                }
            }
        }
    }
}

// ---------------------------------------------------------------------------
// softmax over NSC=999 (fp16 scores, stride 1024) -> fp16 attn row, eye-shift.
// 256 threads x 4 halves each.
// ---------------------------------------------------------------------------
__global__ __launch_bounds__(256) void k_softmax_attn() {
    int blk = blockIdx.x;
    int b = blk / An;
    int i = blk - b * An;
    const __half* s = g_scoresH + ((long)b * APAD + i) * NPAD;
    __half* arow = g_attnH + ((long)b * APAD + i) * NPAD;
    int tid = threadIdx.x;
    __shared__ float red[8];

    const int c4 = tid * 4;
    __half2 h01 = *reinterpret_cast<const __half2*>(s + c4);
    __half2 h23 = *reinterpret_cast<const __half2*>(s + c4 + 2);
    float vv[4] = { __low2float(h01), __high2float(h01),
                    __low2float(h23), __high2float(h23) };

    float mx = -3.4e38f;
#pragma unroll
    for (int e = 0; e < 4; e++)
        if (c4 + e < NSC) mx = fmaxf(mx, vv[e]);
#pragma unroll
    for (int o = 16; o; o >>= 1) mx = fmaxf(mx, __shfl_xor_sync(0xffffffffu, mx, o));
    if ((tid & 31) == 0) red[tid >> 5] = mx;
    __syncthreads();
    mx = red[0];
#pragma unroll
    for (int w = 1; w < 8; w++) mx = fmaxf(mx, red[w]);
    __syncthreads();

    float ex[4];
    float sum = 0.0f;
#pragma unroll
    for (int e = 0; e < 4; e++) {
        float t = 0.0f;
        if (c4 + e < NSC) { t = __expf(vv[e] - mx); sum += t; }
        ex[e] = t;
    }
#pragma unroll
    for (int o = 16; o; o >>= 1) sum += __shfl_xor_sync(0xffffffffu, sum, o);
    if ((tid & 31) == 0) red[tid >> 5] = sum;
    __syncthreads();
    float tot = red[0];
#pragma unroll
    for (int w = 1; w < 8; w++) tot += red[w];
    float inv = 1.0f / tot;

#pragma unroll
    for (int e = 0; e < 4; e++) {
        int c = c4 + e;
        if (c < NSC) {
            int j = c + (c >= i ? 1 : 0);
            arow[j] = __float2half(ex[e] * inv);
        }
    }
    if (tid == 0) arow[i] = __half(0.0f);
    if (tid >= 250) {                          // zero cols 1000..1023
        int c = 1000 + (tid - 250) * 4;
#pragma unroll
        for (int e = 0; e < 4; e++) arow[c + e] = __half(0.0f);
    }
}

// ---------------------------------------------------------------------------
extern "C" void kernel_launch(void* const* d_in, const int* in_sizes, int n_in,
                              void* d_out, int out_size) {
    const float* fv   = (const float*)d_in[0];
    const int*   z    = (const int*)d_in[1];
    const int*   y    = (const int*)d_in[2];
    const int*   x    = (const int*)d_in[3];
    const int*   inv  = (const int*)d_in[4];
    const float* Wt   = (const float*)d_in[5];
    const float* bias = (const float*)d_in[6];
    float* out = (float*)d_out;

    cudaFuncSetAttribute(k_gemm<true>,  cudaFuncAttributeMaxDynamicSharedMemorySize, SMEM_G);
    cudaFuncSetAttribute(k_gemm<false>, cudaFuncAttributeMaxDynamicSharedMemorySize, SMEM_G);
    cudaFuncSetAttribute(k_gatherT,     cudaFuncAttributeMaxDynamicSharedMemorySize, GT_SMEM);

    k_precomp<<<(An * CHn + 255) / 256, 256>>>(z, y, x, inv);
    k_WT<<<(APAD * CHn + 255) / 256, 256>>>(Wt, bias);
    k_gatherT<<<dim3(APAD / 32, Bn), 256, GT_SMEM>>>(fv);
    k_gemm<true><<<dim3(NPAD / 256, MtotPad / 128), 256, SMEM_G>>>(nullptr);
    k_softmax_attn<<<Bn * An, 256>>>();
    k_gemm<false><<<dim3(CHn / 256, APAD / 128, Bn), 256, SMEM_G>>>(out);
}

// round 14
// speedup vs baseline: 1.1089x; 1.1089x over previous
#include <cuda_runtime.h>
#include <cuda_fp16.h>
#include <cstdint>

// ---------------------------------------------------------------------------
// LaneATT — fp16 mma.sync m16n8k16, 128x256 blocks (warp 64x64), BK=64,
// 4-stage cp.async ring, fp16 scores. Separate gather + transpose kernels.
//   B=32, A=1000 (pad 1024), CH=768, NSC=999 (pad 1024)
//   1) gather index; W^T -> fp16 [n][k]; padded fp32 bias
//   2) gather feats -> fp16 [b][1024][768]; transpose -> featsT [b][768][1024]
//   3) GEMM1: scores(fp16, stride 1024) = feats @ W + b  (32768 x 1024, K=768)
//   4) softmax(999) -> attn fp16 [b][1024][1024], eye-shift
//   5) GEMM2: out[b] = attn[b] @ feats[b]                (1024 x 768, K=1024)
// ---------------------------------------------------------------------------

static constexpr int Bn  = 32;
static constexpr int An  = 1000;
static constexpr int APAD = 1024;
static constexpr int Cn  = 64;
static constexpr int Hn  = 12;
static constexpr int Wn  = 20;
static constexpr int CHn = Cn * Hn;        // 768
static constexpr int NSC = An - 1;         // 999
static constexpr int NPAD = 1024;
static constexpr int FVB = Cn * Hn * Wn;   // 15360
static constexpr int MtotPad = Bn * APAD;  // 32768

__device__ __half g_featsH[Bn * APAD * CHn];       // 48 MB  [b][a][ch]
__device__ __half g_featsTH[Bn * CHn * APAD];      // 48 MB  [b][ch][a]
__device__ __half g_attnH[Bn * APAD * NPAD];       // 64 MB  [b][i][j]
__device__ __half g_scoresH[(long)MtotPad * NPAD]; // 64 MB  padded stride
__device__ __half g_WTH[APAD * CHn];               // 1.5 MB [n][k]
__device__ float  g_biasPad[NPAD];
__device__ int    g_comb[An * CHn];

// ---------------------------------------------------------------------------
__device__ __forceinline__ uint32_t smem_u32(const void* p) {
    return (uint32_t)__cvta_generic_to_shared(p);
}
__device__ __forceinline__ void cpa16(uint32_t dst, const void* src) {
    asm volatile("cp.async.cg.shared.global [%0], [%1], 16;\n" :: "r"(dst), "l"(src));
}
#define CP_COMMIT() asm volatile("cp.async.commit_group;\n" ::: "memory")
#define CP_WAIT2()  asm volatile("cp.async.wait_group 2;\n" ::: "memory")
#define CP_WAIT1()  asm volatile("cp.async.wait_group 1;\n" ::: "memory")
#define CP_WAIT0()  asm volatile("cp.async.wait_group 0;\n" ::: "memory")

__device__ __forceinline__ void ldsm_x4(uint32_t* r, uint32_t addr) {
    asm volatile("ldmatrix.sync.aligned.m8n8.x4.shared.b16 {%0,%1,%2,%3}, [%4];"
                 : "=r"(r[0]), "=r"(r[1]), "=r"(r[2]), "=r"(r[3]) : "r"(addr));
}
__device__ __forceinline__ void ldsm_x2(uint32_t* r, uint32_t addr) {
    asm volatile("ldmatrix.sync.aligned.m8n8.x2.shared.b16 {%0,%1}, [%2];"
                 : "=r"(r[0]), "=r"(r[1]) : "r"(addr));
}
__device__ __forceinline__ void mma16(float* c, const uint32_t* a, const uint32_t* b) {
    asm volatile(
        "mma.sync.aligned.m16n8k16.row.col.f32.f16.f16.f32 "
        "{%0,%1,%2,%3}, {%4,%5,%6,%7}, {%8,%9}, {%0,%1,%2,%3};\n"
        : "+f"(c[0]), "+f"(c[1]), "+f"(c[2]), "+f"(c[3])
        : "r"(a[0]), "r"(a[1]), "r"(a[2]), "r"(a[3]), "r"(b[0]), "r"(b[1]));
}

// ---------------------------------------------------------------------------
// prep kernels
// ---------------------------------------------------------------------------
__global__ void k_precomp(const int* __restrict__ z, const int* __restrict__ y,
                          const int* __restrict__ x, const int* __restrict__ inv) {
    int i = blockIdx.x * blockDim.x + threadIdx.x;
    if (i >= An * CHn) return;
    g_comb[i] = inv[i] ? -1 : (z[i] * (Hn * Wn) + y[i] * Wn + x[i]);
}

__global__ void k_WT(const float* __restrict__ Wt, const float* __restrict__ bias) {
    int i = blockIdx.x * blockDim.x + threadIdx.x;
    if (i >= APAD * CHn) return;
    int n = i / CHn, k = i - n * CHn;
    g_WTH[i] = (n < NSC) ? __float2half(__ldg(Wt + (long)k * NSC + n)) : __half(0.0f);
    if (i < NPAD) g_biasPad[i] = (i < NSC) ? __ldg(bias + i) : 0.0f;
}

__global__ void k_gather(const float* __restrict__ fv) {
    int a = blockIdx.x;
    int b = blockIdx.y;
    const float* fvb = fv + b * FVB;
    const int*   cmb = g_comb + a * CHn;
    __half2*     out = reinterpret_cast<__half2*>(g_featsH + ((long)b * APAD + a) * CHn);
    for (int p = threadIdx.x; p < CHn / 2; p += blockDim.x) {
        int i0 = cmb[2 * p], i1 = cmb[2 * p + 1];
        float f0 = (i0 < 0) ? 0.0f : __ldg(fvb + i0);
        float f1 = (i1 < 0) ? 0.0f : __ldg(fvb + i1);
        out[p] = __floats2half2_rn(f0, f1);
    }
}

// tiled transpose featsH -> featsTH (pad rows a>=1000 are zero; transpose too)
__global__ void k_transpose() {
    __shared__ __half t[32][40];
    int b  = blockIdx.z;
    int a0 = blockIdx.x * 32;
    int c0 = blockIdx.y * 32;
    int tx = threadIdx.x, ty = threadIdx.y;       // 32 x 8
    const __half* F  = g_featsH + (long)b * APAD * CHn;
    __half*       FT = g_featsTH + (long)b * CHn * APAD;
#pragma unroll
    for (int i = 0; i < 32; i += 8)
        t[ty + i][tx] = F[(long)(a0 + ty + i) * CHn + c0 + tx];
    __syncthreads();
#pragma unroll
    for (int i = 0; i < 32; i += 8)
        FT[(long)(c0 + ty + i) * APAD + a0 + tx] = t[tx][ty + i];
}

// ---------------------------------------------------------------------------
// GEMM: D[128 x 256] = A[128 x K] @ B[256 rows x K]^T (both K-major), fp16 in,
// fp32 accum. 8 warps (2x4), warp tile 64x64, BK=64, 4-stage cp.async ring.
//  G1: A=featsH  lda=768,  B=WTH     ldb=768,  K=768  -> scoresH(+bias) fp16
//  G2: A=attnH   lda=1024, B=featsTH ldb=1024, K=1024 -> out fp32 (row guard)
// ---------------------------------------------------------------------------
static constexpr int ROWB = 144;                 // smem row: 128B data + 16 pad
static constexpr int A_TB = 128 * ROWB;          // 18432
static constexpr int B_TB = 256 * ROWB;          // 36864
static constexpr int STG  = A_TB + B_TB;         // 55296
static constexpr int SMEM_G = 4 * STG;           // 221184

template <bool G1>
__global__ __launch_bounds__(256, 1) void k_gemm(float* __restrict__ out) {
    constexpr int NS = G1 ? (CHn / 64) : (APAD / 64);   // 12 / 16

    extern __shared__ char smem[];
    uint32_t sb = smem_u32(smem);

    const int tid = threadIdx.x;
    const int warp = tid >> 5, lane = tid & 31;
    const int wm = warp >> 2, wn = warp & 3;     // 2 x 4 warps -> 64x64 tiles
    const int m0 = blockIdx.y * 128;
    const int n0 = blockIdx.x * 256;

    const __half* Ag;
    const __half* Bg;
    long lda, ldb;
    if (G1) { Ag = g_featsH; Bg = g_WTH; lda = CHn; ldb = CHn; }
    else {
        int b = blockIdx.z;
        Ag = g_attnH + (long)b * APAD * NPAD;
        Bg = g_featsTH + (long)b * CHn * APAD;
        lda = NPAD; ldb = APAD;
    }

    auto load_stage = [&](int s, int buf) {
        int k0 = s * 64;
        uint32_t ab = sb + buf * STG;
        uint32_t bb = ab + A_TB;
#pragma unroll
        for (int i = 0; i < 4; i++) {            // A: 1024 cp.async
            int idx = tid + i * 256;
            int row = idx >> 3, ch = idx & 7;
            cpa16(ab + row * ROWB + ch * 16,
                  Ag + (long)(m0 + row) * lda + k0 + ch * 8);
        }
#pragma unroll
        for (int i = 0; i < 8; i++) {            // B: 2048 cp.async
            int idx = tid + i * 256;
            int row = idx >> 3, ch = idx & 7;
            cpa16(bb + row * ROWB + ch * 16,
                  Bg + (long)(n0 + row) * ldb + k0 + ch * 8);
        }
    };

    float acc[4][8][4];
#pragma unroll
    for (int i = 0; i < 4; i++)
#pragma unroll
        for (int j = 0; j < 8; j++)
#pragma unroll
            for (int v = 0; v < 4; v++) acc[i][j][v] = 0.0f;

    load_stage(0, 0); CP_COMMIT();
    load_stage(1, 1); CP_COMMIT();
    load_stage(2, 2); CP_COMMIT();

    const int l15 = lane & 15;
    const int ahi = (lane >> 4) << 4;        // +16B: k upper half for lanes 16-31
    const int bhi = ((lane >> 3) & 1) << 4;  // +16B: k upper 8 for lanes 8-15

    for (int s = 0; s < NS; s++) {
        if (s + 2 < NS) CP_WAIT2();
        else if (s + 1 < NS) CP_WAIT1();
        else CP_WAIT0();
        __syncthreads();

        uint32_t ab = sb + (s & 3) * STG;
        uint32_t bb = ab + A_TB;
#pragma unroll
        for (int kk = 0; kk < 4; kk++) {
            uint32_t af[4][4], bf[8][2];
#pragma unroll
            for (int mt = 0; mt < 4; mt++) {
                int row = wm * 64 + mt * 16 + l15;
                ldsm_x4(af[mt], ab + row * ROWB + kk * 32 + ahi);
            }
#pragma unroll
            for (int nt = 0; nt < 8; nt++) {
                int nr = wn * 64 + nt * 8 + (l15 & 7);
                ldsm_x2(bf[nt], bb + nr * ROWB + kk * 32 + bhi);
            }
#pragma unroll
            for (int mt = 0; mt < 4; mt++)
#pragma unroll
                for (int nt = 0; nt < 8; nt++)
                    mma16(acc[mt][nt], af[mt], bf[nt]);
        }

        if (s + 3 < NS) { load_stage(s + 3, (s + 3) & 3); CP_COMMIT(); }
    }

    // epilogue: c{0,1} -> (row g, cols 2t,2t+1); c{2,3} -> row g+8
    const int g = lane >> 2, t4 = lane & 3;
#pragma unroll
    for (int mt = 0; mt < 4; mt++) {
#pragma unroll
        for (int nt = 0; nt < 8; nt++) {
            int row = m0 + wm * 64 + mt * 16 + g;
            int col = n0 + wn * 64 + nt * 8 + t4 * 2;
            if (G1) {
                float2 bv = *reinterpret_cast<const float2*>(g_biasPad + col);
#pragma unroll
                for (int h = 0; h < 2; h++) {
                    __half2 hv = __floats2half2_rn(acc[mt][nt][h * 2] + bv.x,
                                                   acc[mt][nt][h * 2 + 1] + bv.y);
                    *reinterpret_cast<__half2*>(
                        g_scoresH + (long)(row + h * 8) * NPAD + col) = hv;
                }
            } else {
#pragma unroll
                for (int h = 0; h < 2; h++) {
                    int r = row + h * 8;
                    if (r < An) {
                        float2 v = make_float2(acc[mt][nt][h * 2], acc[mt][nt][h * 2 + 1]);
                        *reinterpret_cast<float2*>(
                            out + ((long)blockIdx.z * An + r) * CHn + col) = v;
                    }
                }
            }
        }
    }
}

// ---------------------------------------------------------------------------
// softmax over NSC=999 (fp16 scores, stride 1024) -> fp16 attn row, eye-shift.
// 256 threads x 4 halves each.
// ---------------------------------------------------------------------------
__global__ __launch_bounds__(256) void k_softmax_attn() {
    int blk = blockIdx.x;
    int b = blk / An;
    int i = blk - b * An;
    const __half* s = g_scoresH + ((long)b * APAD + i) * NPAD;
    __half* arow = g_attnH + ((long)b * APAD + i) * NPAD;
    int tid = threadIdx.x;
    __shared__ float red[8];

    const int c4 = tid * 4;
    __half2 h01 = *reinterpret_cast<const __half2*>(s + c4);
    __half2 h23 = *reinterpret_cast<const __half2*>(s + c4 + 2);
    float vv[4] = { __low2float(h01), __high2float(h01),
                    __low2float(h23), __high2float(h23) };

    float mx = -3.4e38f;
#pragma unroll
    for (int e = 0; e < 4; e++)
        if (c4 + e < NSC) mx = fmaxf(mx, vv[e]);
#pragma unroll
    for (int o = 16; o; o >>= 1) mx = fmaxf(mx, __shfl_xor_sync(0xffffffffu, mx, o));
    if ((tid & 31) == 0) red[tid >> 5] = mx;
    __syncthreads();
    mx = red[0];
#pragma unroll
    for (int w = 1; w < 8; w++) mx = fmaxf(mx, red[w]);
    __syncthreads();

    float ex[4];
    float sum = 0.0f;
#pragma unroll
    for (int e = 0; e < 4; e++) {
        float t = 0.0f;
        if (c4 + e < NSC) { t = __expf(vv[e] - mx); sum += t; }
        ex[e] = t;
    }
#pragma unroll
    for (int o = 16; o; o >>= 1) sum += __shfl_xor_sync(0xffffffffu, sum, o);
    if ((tid & 31) == 0) red[tid >> 5] = sum;
    __syncthreads();
    float tot = red[0];
#pragma unroll
    for (int w = 1; w < 8; w++) tot += red[w];
    float inv = 1.0f / tot;

#pragma unroll
    for (int e = 0; e < 4; e++) {
        int c = c4 + e;
        if (c < NSC) {
            int j = c + (c >= i ? 1 : 0);
            arow[j] = __float2half(ex[e] * inv);
        }
    }
    if (tid == 0) arow[i] = __half(0.0f);
    if (tid >= 250) {                          // zero cols 1000..1023
        int c = 1000 + (tid - 250) * 4;
#pragma unroll
        for (int e = 0; e < 4; e++) arow[c + e] = __half(0.0f);
    }
}

// ---------------------------------------------------------------------------
extern "C" void kernel_launch(void* const* d_in, const int* in_sizes, int n_in,
                              void* d_out, int out_size) {
    const float* fv   = (const float*)d_in[0];
    const int*   z    = (const int*)d_in[1];
    const int*   y    = (const int*)d_in[2];
    const int*   x    = (const int*)d_in[3];
    const int*   inv  = (const int*)d_in[4];
    const float* Wt   = (const float*)d_in[5];
    const float* bias = (const float*)d_in[6];
    float* out = (float*)d_out;

    cudaFuncSetAttribute(k_gemm<true>,  cudaFuncAttributeMaxDynamicSharedMemorySize, SMEM_G);
    cudaFuncSetAttribute(k_gemm<false>, cudaFuncAttributeMaxDynamicSharedMemorySize, SMEM_G);

    k_precomp<<<(An * CHn + 255) / 256, 256>>>(z, y, x, inv);
    k_WT<<<(APAD * CHn + 255) / 256, 256>>>(Wt, bias);
    k_gather<<<dim3(An, Bn), 256>>>(fv);
    k_transpose<<<dim3(APAD / 32, CHn / 32, Bn), dim3(32, 8)>>>();
    k_gemm<true><<<dim3(NPAD / 256, MtotPad / 128), 256, SMEM_G>>>(nullptr);
    k_softmax_attn<<<Bn * An, 256>>>();
    k_gemm<false><<<dim3(CHn / 256, APAD / 128, Bn), 256, SMEM_G>>>(out);
}

// round 15
// speedup vs baseline: 1.1878x; 1.0711x over previous
#include <cuda_runtime.h>
#include <cuda_fp16.h>
#include <cstdint>

// ---------------------------------------------------------------------------
// LaneATT — fp16 mma.sync m16n8k16, 128x128 blocks (4 warps, warp 64x64),
// BK=64, 3-stage cp.async ring, 2 CTAs/SM, fp16 scores.
//   B=32, A=1000 (pad 1024), CH=768, NSC=999 (pad 1024)
//   1) gather index; W^T -> fp16 [n][k]; padded fp32 bias
//   2) gather feats -> fp16 [b][1024][768]; transpose -> featsT [b][768][1024]
//   3) GEMM1: scores(fp16, stride 1024) = feats @ W + b  (32768 x 1024, K=768)
//   4) softmax(999) -> attn fp16 [b][1024][1024], eye-shift
//   5) GEMM2: out[b] = attn[b] @ feats[b]                (1024 x 768, K=1024)
// ---------------------------------------------------------------------------

static constexpr int Bn  = 32;
static constexpr int An  = 1000;
static constexpr int APAD = 1024;
static constexpr int Cn  = 64;
static constexpr int Hn  = 12;
static constexpr int Wn  = 20;
static constexpr int CHn = Cn * Hn;        // 768
static constexpr int NSC = An - 1;         // 999
static constexpr int NPAD = 1024;
static constexpr int FVB = Cn * Hn * Wn;   // 15360
static constexpr int MtotPad = Bn * APAD;  // 32768

__device__ __half g_featsH[Bn * APAD * CHn];       // 48 MB  [b][a][ch]
__device__ __half g_featsTH[Bn * CHn * APAD];      // 48 MB  [b][ch][a]
__device__ __half g_attnH[Bn * APAD * NPAD];       // 64 MB  [b][i][j]
__device__ __half g_scoresH[(long)MtotPad * NPAD]; // 64 MB  padded stride
__device__ __half g_WTH[APAD * CHn];               // 1.5 MB [n][k]
__device__ float  g_biasPad[NPAD];
__device__ int    g_comb[An * CHn];

// ---------------------------------------------------------------------------
__device__ __forceinline__ uint32_t smem_u32(const void* p) {
    return (uint32_t)__cvta_generic_to_shared(p);
}
__device__ __forceinline__ void cpa16(uint32_t dst, const void* src) {
    asm volatile("cp.async.cg.shared.global [%0], [%1], 16;\n" :: "r"(dst), "l"(src));
}
#define CP_COMMIT() asm volatile("cp.async.commit_group;\n" ::: "memory")
#define CP_WAIT1()  asm volatile("cp.async.wait_group 1;\n" ::: "memory")
#define CP_WAIT0()  asm volatile("cp.async.wait_group 0;\n" ::: "memory")

__device__ __forceinline__ void ldsm_x4(uint32_t* r, uint32_t addr) {
    asm volatile("ldmatrix.sync.aligned.m8n8.x4.shared.b16 {%0,%1,%2,%3}, [%4];"
                 : "=r"(r[0]), "=r"(r[1]), "=r"(r[2]), "=r"(r[3]) : "r"(addr));
}
__device__ __forceinline__ void ldsm_x2(uint32_t* r, uint32_t addr) {
    asm volatile("ldmatrix.sync.aligned.m8n8.x2.shared.b16 {%0,%1}, [%2];"
                 : "=r"(r[0]), "=r"(r[1]) : "r"(addr));
}
__device__ __forceinline__ void mma16(float* c, const uint32_t* a, const uint32_t* b) {
    asm volatile(
        "mma.sync.aligned.m16n8k16.row.col.f32.f16.f16.f32 "
        "{%0,%1,%2,%3}, {%4,%5,%6,%7}, {%8,%9}, {%0,%1,%2,%3};\n"
        : "+f"(c[0]), "+f"(c[1]), "+f"(c[2]), "+f"(c[3])
        : "r"(a[0]), "r"(a[1]), "r"(a[2]), "r"(a[3]), "r"(b[0]), "r"(b[1]));
}

// ---------------------------------------------------------------------------
// prep kernels
// ---------------------------------------------------------------------------
__global__ void k_precomp(const int* __restrict__ z, const int* __restrict__ y,
                          const int* __restrict__ x, const int* __restrict__ inv) {
    int i = blockIdx.x * blockDim.x + threadIdx.x;
    if (i >= An * CHn) return;
    g_comb[i] = inv[i] ? -1 : (z[i] * (Hn * Wn) + y[i] * Wn + x[i]);
}

__global__ void k_WT(const float* __restrict__ Wt, const float* __restrict__ bias) {
    int i = blockIdx.x * blockDim.x + threadIdx.x;
    if (i >= APAD * CHn) return;
    int n = i / CHn, k = i - n * CHn;
    g_WTH[i] = (n < NSC) ? __float2half(__ldg(Wt + (long)k * NSC + n)) : __half(0.0f);
    if (i < NPAD) g_biasPad[i] = (i < NSC) ? __ldg(bias + i) : 0.0f;
}

__global__ void k_gather(const float* __restrict__ fv) {
    int a = blockIdx.x;
    int b = blockIdx.y;
    const float* fvb = fv + b * FVB;
    const int*   cmb = g_comb + a * CHn;
    __half2*     out = reinterpret_cast<__half2*>(g_featsH + ((long)b * APAD + a) * CHn);
    for (int p = threadIdx.x; p < CHn / 2; p += blockDim.x) {
        int i0 = cmb[2 * p], i1 = cmb[2 * p + 1];
        float f0 = (i0 < 0) ? 0.0f : __ldg(fvb + i0);
        float f1 = (i1 < 0) ? 0.0f : __ldg(fvb + i1);
        out[p] = __floats2half2_rn(f0, f1);
    }
}

// tiled transpose featsH -> featsTH (pad rows a>=1000 are zero; transpose too)
__global__ void k_transpose() {
    __shared__ __half t[32][40];
    int b  = blockIdx.z;
    int a0 = blockIdx.x * 32;
    int c0 = blockIdx.y * 32;
    int tx = threadIdx.x, ty = threadIdx.y;       // 32 x 8
    const __half* F  = g_featsH + (long)b * APAD * CHn;
    __half*       FT = g_featsTH + (long)b * CHn * APAD;
#pragma unroll
    for (int i = 0; i < 32; i += 8)
        t[ty + i][tx] = F[(long)(a0 + ty + i) * CHn + c0 + tx];
    __syncthreads();
#pragma unroll
    for (int i = 0; i < 32; i += 8)
        FT[(long)(c0 + ty + i) * APAD + a0 + tx] = t[tx][ty + i];
}

// ---------------------------------------------------------------------------
// GEMM: D[128 x 128] = A[128 x K] @ B[128 rows x K]^T (both K-major), fp16 in,
// fp32 accum. 4 warps (2x2), warp tile 64x64, BK=64, 3-stage ring, 2 CTAs/SM.
//  G1: A=featsH  lda=768,  B=WTH     ldb=768,  K=768  -> scoresH(+bias) fp16
//  G2: A=attnH   lda=1024, B=featsTH ldb=1024, K=1024 -> out fp32 (row guard)
// ---------------------------------------------------------------------------
static constexpr int ROWB = 144;                 // smem row: 128B data + 16 pad
static constexpr int A_TB = 128 * ROWB;          // 18432
static constexpr int B_TB = 128 * ROWB;          // 18432
static constexpr int STG  = A_TB + B_TB;         // 36864
static constexpr int SMEM_G = 3 * STG;           // 110592 (x2 CTAs = 221184)

template <bool G1>
__global__ __launch_bounds__(128, 2) void k_gemm(float* __restrict__ out) {
    constexpr int NS = G1 ? (CHn / 64) : (APAD / 64);   // 12 / 16

    extern __shared__ char smem[];
    uint32_t sb = smem_u32(smem);

    const int tid = threadIdx.x;
    const int warp = tid >> 5, lane = tid & 31;
    const int wm = warp >> 1, wn = warp & 1;     // 2 x 2 warps -> 64x64 tiles
    const int m0 = blockIdx.y * 128;
    const int n0 = blockIdx.x * 128;

    const __half* Ag;
    const __half* Bg;
    long lda, ldb;
    if (G1) { Ag = g_featsH; Bg = g_WTH; lda = CHn; ldb = CHn; }
    else {
        int b = blockIdx.z;
        Ag = g_attnH + (long)b * APAD * NPAD;
        Bg = g_featsTH + (long)b * CHn * APAD;
        lda = NPAD; ldb = APAD;
    }

    auto load_stage = [&](int s, int buf) {
        int k0 = s * 64;
        uint32_t ab = sb + buf * STG;
        uint32_t bb = ab + A_TB;
#pragma unroll
        for (int i = 0; i < 8; i++) {            // A: 1024 cp.async / 128 thr
            int idx = tid + i * 128;
            int row = idx >> 3, ch = idx & 7;
            cpa16(ab + row * ROWB + ch * 16,
                  Ag + (long)(m0 + row) * lda + k0 + ch * 8);
        }
#pragma unroll
        for (int i = 0; i < 8; i++) {            // B: 1024 cp.async / 128 thr
            int idx = tid + i * 128;
            int row = idx >> 3, ch = idx & 7;
            cpa16(bb + row * ROWB + ch * 16,
                  Bg + (long)(n0 + row) * ldb + k0 + ch * 8);
        }
    };

    float acc[4][8][4];
#pragma unroll
    for (int i = 0; i < 4; i++)
#pragma unroll
        for (int j = 0; j < 8; j++)
#pragma unroll
            for (int v = 0; v < 4; v++) acc[i][j][v] = 0.0f;

    load_stage(0, 0); CP_COMMIT();
    load_stage(1, 1); CP_COMMIT();

    const int l15 = lane & 15;
    const int ahi = (lane >> 4) << 4;        // +16B: k upper half for lanes 16-31
    const int bhi = ((lane >> 3) & 1) << 4;  // +16B: k upper 8 for lanes 8-15

    for (int s = 0; s < NS; s++) {
        if (s + 1 < NS) CP_WAIT1(); else CP_WAIT0();
        __syncthreads();

        uint32_t ab = sb + (s % 3) * STG;
        uint32_t bb = ab + A_TB;
#pragma unroll
        for (int kk = 0; kk < 4; kk++) {
            uint32_t af[4][4], bf[8][2];
#pragma unroll
            for (int mt = 0; mt < 4; mt++) {
                int row = wm * 64 + mt * 16 + l15;
                ldsm_x4(af[mt], ab + row * ROWB + kk * 32 + ahi);
            }
#pragma unroll
            for (int nt = 0; nt < 8; nt++) {
                int nr = wn * 64 + nt * 8 + (l15 & 7);
                ldsm_x2(bf[nt], bb + nr * ROWB + kk * 32 + bhi);
            }
#pragma unroll
            for (int mt = 0; mt < 4; mt++)
#pragma unroll
                for (int nt = 0; nt < 8; nt++)
                    mma16(acc[mt][nt], af[mt], bf[nt]);
        }

        if (s + 2 < NS) { load_stage(s + 2, (s + 2) % 3); CP_COMMIT(); }
    }

    // epilogue: c{0,1} -> (row g, cols 2t,2t+1); c{2,3} -> row g+8
    const int g = lane >> 2, t4 = lane & 3;
#pragma unroll
    for (int mt = 0; mt < 4; mt++) {
#pragma unroll
        for (int nt = 0; nt < 8; nt++) {
            int row = m0 + wm * 64 + mt * 16 + g;
            int col = n0 + wn * 64 + nt * 8 + t4 * 2;
            if (G1) {
                float2 bv = *reinterpret_cast<const float2*>(g_biasPad + col);
#pragma unroll
                for (int h = 0; h < 2; h++) {
                    __half2 hv = __floats2half2_rn(acc[mt][nt][h * 2] + bv.x,
                                                   acc[mt][nt][h * 2 + 1] + bv.y);
                    *reinterpret_cast<__half2*>(
                        g_scoresH + (long)(row + h * 8) * NPAD + col) = hv;
                }
            } else {
#pragma unroll
                for (int h = 0; h < 2; h++) {
                    int r = row + h * 8;
                    if (r < An) {
                        float2 v = make_float2(acc[mt][nt][h * 2], acc[mt][nt][h * 2 + 1]);
                        *reinterpret_cast<float2*>(
                            out + ((long)blockIdx.z * An + r) * CHn + col) = v;
                    }
                }
            }
        }
    }
}

// ---------------------------------------------------------------------------
// softmax over NSC=999 (fp16 scores, stride 1024) -> fp16 attn row, eye-shift.
// 256 threads x 4 halves each.
// ---------------------------------------------------------------------------
__global__ __launch_bounds__(256) void k_softmax_attn() {
    int blk = blockIdx.x;
    int b = blk / An;
    int i = blk - b * An;
    const __half* s = g_scoresH + ((long)b * APAD + i) * NPAD;
    __half* arow = g_attnH + ((long)b * APAD + i) * NPAD;
    int tid = threadIdx.x;
    __shared__ float red[8];

    const int c4 = tid * 4;
    __half2 h01 = *reinterpret_cast<const __half2*>(s + c4);
    __half2 h23 = *reinterpret_cast<const __half2*>(s + c4 + 2);
    float vv[4] = { __low2float(h01), __high2float(h01),
                    __low2float(h23), __high2float(h23) };

    float mx = -3.4e38f;
#pragma unroll
    for (int e = 0; e < 4; e++)
        if (c4 + e < NSC) mx = fmaxf(mx, vv[e]);
#pragma unroll
    for (int o = 16; o; o >>= 1) mx = fmaxf(mx, __shfl_xor_sync(0xffffffffu, mx, o));
    if ((tid & 31) == 0) red[tid >> 5] = mx;
    __syncthreads();
    mx = red[0];
#pragma unroll
    for (int w = 1; w < 8; w++) mx = fmaxf(mx, red[w]);
    __syncthreads();

    float ex[4];
    float sum = 0.0f;
#pragma unroll
    for (int e = 0; e < 4; e++) {
        float t = 0.0f;
        if (c4 + e < NSC) { t = __expf(vv[e] - mx); sum += t; }
        ex[e] = t;
    }
#pragma unroll
    for (int o = 16; o; o >>= 1) sum += __shfl_xor_sync(0xffffffffu, sum, o);
    if ((tid & 31) == 0) red[tid >> 5] = sum;
    __syncthreads();
    float tot = red[0];
#pragma unroll
    for (int w = 1; w < 8; w++) tot += red[w];
    float inv = 1.0f / tot;

#pragma unroll
    for (int e = 0; e < 4; e++) {
        int c = c4 + e;
        if (c < NSC) {
            int j = c + (c >= i ? 1 : 0);
            arow[j] = __float2half(ex[e] * inv);
        }
    }
    if (tid == 0) arow[i] = __half(0.0f);
    if (tid >= 250) {                          // zero cols 1000..1023
        int c = 1000 + (tid - 250) * 4;
#pragma unroll
        for (int e = 0; e < 4; e++) arow[c + e] = __half(0.0f);
    }
}

// ---------------------------------------------------------------------------
extern "C" void kernel_launch(void* const* d_in, const int* in_sizes, int n_in,
                              void* d_out, int out_size) {
    const float* fv   = (const float*)d_in[0];
    const int*   z    = (const int*)d_in[1];
    const int*   y    = (const int*)d_in[2];
    const int*   x    = (const int*)d_in[3];
    const int*   inv  = (const int*)d_in[4];
    const float* Wt   = (const float*)d_in[5];
    const float* bias = (const float*)d_in[6];
    float* out = (float*)d_out;

    cudaFuncSetAttribute(k_gemm<true>,  cudaFuncAttributeMaxDynamicSharedMemorySize, SMEM_G);
    cudaFuncSetAttribute(k_gemm<false>, cudaFuncAttributeMaxDynamicSharedMemorySize, SMEM_G);

    k_precomp<<<(An * CHn + 255) / 256, 256>>>(z, y, x, inv);
    k_WT<<<(APAD * CHn + 255) / 256, 256>>>(Wt, bias);
    k_gather<<<dim3(An, Bn), 256>>>(fv);
    k_transpose<<<dim3(APAD / 32, CHn / 32, Bn), dim3(32, 8)>>>();
    k_gemm<true><<<dim3(NPAD / 128, MtotPad / 128), 128, SMEM_G>>>(nullptr);
    k_softmax_attn<<<Bn * An, 256>>>();
    k_gemm<false><<<dim3(CHn / 128, APAD / 128, Bn), 128, SMEM_G>>>(out);
}

// round 17
// speedup vs baseline: 1.2117x; 1.0201x over previous
#include <cuda_runtime.h>
#include <cuda_fp16.h>
#include <cstdint>

// ---------------------------------------------------------------------------
// LaneATT — fp16 mma.sync m16n8k16, 128x128 blocks (4 warps, warp 64x64),
// BK=64, 3-stage cp.async ring, 2 CTAs/SM, fp16 scores, fragment
// double-buffering in the mainloop. K-major B tiles (W^T, feats^T).
//   B=32, A=1000 (pad 1024), CH=768, NSC=999 (pad 1024)
//   1) gather index; W^T -> fp16 [n][k]; padded fp32 bias
//   2) gather feats -> fp16 [b][1024][768]; transpose -> featsT [b][768][1024]
//   3) GEMM1: scores(fp16, stride 1024) = feats @ W + b  (32768 x 1024, K=768)
//   4) softmax(999) -> attn fp16 [b][1024][1024], eye-shift
//   5) GEMM2: out[b] = attn[b] @ feats[b]                (1024 x 768, K=1024)
// ---------------------------------------------------------------------------

static constexpr int Bn  = 32;
static constexpr int An  = 1000;
static constexpr int APAD = 1024;
static constexpr int Cn  = 64;
static constexpr int Hn  = 12;
static constexpr int Wn  = 20;
static constexpr int CHn = Cn * Hn;        // 768
static constexpr int NSC = An - 1;         // 999
static constexpr int NPAD = 1024;
static constexpr int FVB = Cn * Hn * Wn;   // 15360
static constexpr int MtotPad = Bn * APAD;  // 32768

__device__ __half g_featsH[Bn * APAD * CHn];       // 48 MB  [b][a][ch]
__device__ __half g_featsTH[Bn * CHn * APAD];      // 48 MB  [b][ch][a]
__device__ __half g_attnH[Bn * APAD * NPAD];       // 64 MB  [b][i][j]
__device__ __half g_scoresH[(long)MtotPad * NPAD]; // 64 MB  padded stride
__device__ __half g_WTH[APAD * CHn];               // 1.5 MB [n][k]
__device__ float  g_biasPad[NPAD];
__device__ int    g_comb[An * CHn];

// ---------------------------------------------------------------------------
__device__ __forceinline__ uint32_t smem_u32(const void* p) {
    return (uint32_t)__cvta_generic_to_shared(p);
}
__device__ __forceinline__ void cpa16(uint32_t dst, const void* src) {
    asm volatile("cp.async.cg.shared.global [%0], [%1], 16;\n" :: "r"(dst), "l"(src));
}
#define CP_COMMIT() asm volatile("cp.async.commit_group;\n" ::: "memory")
#define CP_WAIT1()  asm volatile("cp.async.wait_group 1;\n" ::: "memory")
#define CP_WAIT0()  asm volatile("cp.async.wait_group 0;\n" ::: "memory")

__device__ __forceinline__ void ldsm_x4(uint32_t* r, uint32_t addr) {
    asm volatile("ldmatrix.sync.aligned.m8n8.x4.shared.b16 {%0,%1,%2,%3}, [%4];"
                 : "=r"(r[0]), "=r"(r[1]), "=r"(r[2]), "=r"(r[3]) : "r"(addr));
}
__device__ __forceinline__ void ldsm_x2(uint32_t* r, uint32_t addr) {
    asm volatile("ldmatrix.sync.aligned.m8n8.x2.shared.b16 {%0,%1}, [%2];"
                 : "=r"(r[0]), "=r"(r[1]) : "r"(addr));
}
__device__ __forceinline__ void mma16(float* c, const uint32_t* a, const uint32_t* b) {
    asm volatile(
        "mma.sync.aligned.m16n8k16.row.col.f32.f16.f16.f32 "
        "{%0,%1,%2,%3}, {%4,%5,%6,%7}, {%8,%9}, {%0,%1,%2,%3};\n"
        : "+f"(c[0]), "+f"(c[1]), "+f"(c[2]), "+f"(c[3])
        : "r"(a[0]), "r"(a[1]), "r"(a[2]), "r"(a[3]), "r"(b[0]), "r"(b[1]));
}

// ---------------------------------------------------------------------------
// prep kernels
// ---------------------------------------------------------------------------
__global__ void k_precomp(const int* __restrict__ z, const int* __restrict__ y,
                          const int* __restrict__ x, const int* __restrict__ inv) {
    int i = blockIdx.x * blockDim.x + threadIdx.x;
    if (i >= An * CHn) return;
    g_comb[i] = inv[i] ? -1 : (z[i] * (Hn * Wn) + y[i] * Wn + x[i]);
}

__global__ void k_WT(const float* __restrict__ Wt, const float* __restrict__ bias) {
    int i = blockIdx.x * blockDim.x + threadIdx.x;
    if (i >= APAD * CHn) return;
    int n = i / CHn, k = i - n * CHn;
    g_WTH[i] = (n < NSC) ? __float2half(__ldg(Wt + (long)k * NSC + n)) : __half(0.0f);
    if (i < NPAD) g_biasPad[i] = (i < NSC) ? __ldg(bias + i) : 0.0f;
}

__global__ void k_gather(const float* __restrict__ fv) {
    int a = blockIdx.x;
    int b = blockIdx.y;
    const float* fvb = fv + b * FVB;
    const int*   cmb = g_comb + a * CHn;
    __half2*     out = reinterpret_cast<__half2*>(g_featsH + ((long)b * APAD + a) * CHn);
    for (int p = threadIdx.x; p < CHn / 2; p += blockDim.x) {
        int i0 = cmb[2 * p], i1 = cmb[2 * p + 1];
        float f0 = (i0 < 0) ? 0.0f : __ldg(fvb + i0);
        float f1 = (i1 < 0) ? 0.0f : __ldg(fvb + i1);
        out[p] = __floats2half2_rn(f0, f1);
    }
}

// tiled transpose featsH -> featsTH (pad rows a>=1000 are zero; transpose too)
__global__ void k_transpose() {
    __shared__ __half t[32][40];
    int b  = blockIdx.z;
    int a0 = blockIdx.x * 32;
    int c0 = blockIdx.y * 32;
    int tx = threadIdx.x, ty = threadIdx.y;       // 32 x 8
    const __half* F  = g_featsH + (long)b * APAD * CHn;
    __half*       FT = g_featsTH + (long)b * CHn * APAD;
#pragma unroll
    for (int i = 0; i < 32; i += 8)
        t[ty + i][tx] = F[(long)(a0 + ty + i) * CHn + c0 + tx];
    __syncthreads();
#pragma unroll
    for (int i = 0; i < 32; i += 8)
        FT[(long)(c0 + ty + i) * APAD + a0 + tx] = t[tx][ty + i];
}

// ---------------------------------------------------------------------------
// GEMM: D[128 x 128] = A[128 x K] @ B[128 rows x K]^T (both K-major), fp16 in,
// fp32 accum. 4 warps (2x2), warp tile 64x64, BK=64, 3-stage ring, 2 CTAs/SM.
// Fragment double-buffering: LDSM for kk+1 issued before MMAs of kk.
//  G1: A=featsH  lda=768,  B=WTH     ldb=768,  K=768  -> scoresH(+bias) fp16
//  G2: A=attnH   lda=1024, B=featsTH ldb=1024, K=1024 -> out fp32 (row guard)
// ---------------------------------------------------------------------------
static constexpr int ROWB = 144;                 // smem row: 128B data + 16 pad
static constexpr int A_TB = 128 * ROWB;          // 18432
static constexpr int B_TB = 128 * ROWB;          // 18432
static constexpr int STG  = A_TB + B_TB;         // 36864
static constexpr int SMEM_G = 3 * STG;           // 110592 (x2 CTAs = 221184)

template <bool G1>
__global__ __launch_bounds__(128, 2) void k_gemm(float* __restrict__ out) {
    constexpr int NS = G1 ? (CHn / 64) : (APAD / 64);   // 12 / 16

    extern __shared__ char smem[];
    uint32_t sb = smem_u32(smem);

    const int tid = threadIdx.x;
    const int warp = tid >> 5, lane = tid & 31;
    const int wm = warp >> 1, wn = warp & 1;     // 2 x 2 warps -> 64x64 tiles
    const int m0 = blockIdx.y * 128;
    const int n0 = blockIdx.x * 128;

    const __half* Ag;
    const __half* Bg;
    long lda, ldb;
    if (G1) { Ag = g_featsH; Bg = g_WTH; lda = CHn; ldb = CHn; }
    else {
        int b = blockIdx.z;
        Ag = g_attnH + (long)b * APAD * NPAD;
        Bg = g_featsTH + (long)b * CHn * APAD;
        lda = NPAD; ldb = APAD;
    }

    auto load_stage = [&](int s, int buf) {
        int k0 = s * 64;
        uint32_t ab = sb + buf * STG;
        uint32_t bb = ab + A_TB;
#pragma unroll
        for (int i = 0; i < 8; i++) {            // A: 1024 cp.async / 128 thr
            int idx = tid + i * 128;
            int row = idx >> 3, ch = idx & 7;
            cpa16(ab + row * ROWB + ch * 16,
                  Ag + (long)(m0 + row) * lda + k0 + ch * 8);
        }
#pragma unroll
        for (int i = 0; i < 8; i++) {            // B: 1024 cp.async / 128 thr
            int idx = tid + i * 128;
            int row = idx >> 3, ch = idx & 7;
            cpa16(bb + row * ROWB + ch * 16,
                  Bg + (long)(n0 + row) * ldb + k0 + ch * 8);
        }
    };

    float acc[4][8][4];
#pragma unroll
    for (int i = 0; i < 4; i++)
#pragma unroll
        for (int j = 0; j < 8; j++)
#pragma unroll
            for (int v = 0; v < 4; v++) acc[i][j][v] = 0.0f;

    load_stage(0, 0); CP_COMMIT();
    load_stage(1, 1); CP_COMMIT();

    const int l15 = lane & 15;
    const int ahi = (lane >> 4) << 4;        // +16B: k upper half for lanes 16-31
    const int bhi = ((lane >> 3) & 1) << 4;  // +16B: k upper 8 for lanes 8-15

    uint32_t af[2][4][4], bf[2][8][2];

    auto frag_load = [&](uint32_t ab, uint32_t bb, int kk, int pb) {
#pragma unroll
        for (int mt = 0; mt < 4; mt++) {
            int row = wm * 64 + mt * 16 + l15;
            ldsm_x4(af[pb][mt], ab + row * ROWB + kk * 32 + ahi);
        }
#pragma unroll
        for (int nt = 0; nt < 8; nt++) {
            int nr = wn * 64 + nt * 8 + (l15 & 7);
            ldsm_x2(bf[pb][nt], bb + nr * ROWB + kk * 32 + bhi);
        }
    };

    for (int s = 0; s < NS; s++) {
        if (s + 1 < NS) CP_WAIT1(); else CP_WAIT0();
        __syncthreads();

        uint32_t ab = sb + (s % 3) * STG;
        uint32_t bb = ab + A_TB;

        frag_load(ab, bb, 0, 0);
#pragma unroll
        for (int kk = 0; kk < 4; kk++) {
            int cur = kk & 1;
            if (kk + 1 < 4) frag_load(ab, bb, kk + 1, cur ^ 1);
#pragma unroll
            for (int mt = 0; mt < 4; mt++)
#pragma unroll
                for (int nt = 0; nt < 8; nt++)
                    mma16(acc[mt][nt], af[cur][mt], bf[cur][nt]);
        }

        if (s + 2 < NS) { load_stage(s + 2, (s + 2) % 3); CP_COMMIT(); }
    }

    // epilogue: c{0,1} -> (row g, cols 2t,2t+1); c{2,3} -> row g+8
    const int g = lane >> 2, t4 = lane & 3;
#pragma unroll
    for (int mt = 0; mt < 4; mt++) {
#pragma unroll
        for (int nt = 0; nt < 8; nt++) {
            int row = m0 + wm * 64 + mt * 16 + g;
            int col = n0 + wn * 64 + nt * 8 + t4 * 2;
            if (G1) {
                float2 bv = *reinterpret_cast<const float2*>(g_biasPad + col);
#pragma unroll
                for (int h = 0; h < 2; h++) {
                    __half2 hv = __floats2half2_rn(acc[mt][nt][h * 2] + bv.x,
                                                   acc[mt][nt][h * 2 + 1] + bv.y);
                    *reinterpret_cast<__half2*>(
                        g_scoresH + (long)(row + h * 8) * NPAD + col) = hv;
                }
            } else {
#pragma unroll
                for (int h = 0; h < 2; h++) {
                    int r = row + h * 8;
                    if (r < An) {
                        float2 v = make_float2(acc[mt][nt][h * 2], acc[mt][nt][h * 2 + 1]);
                        *reinterpret_cast<float2*>(
                            out + ((long)blockIdx.z * An + r) * CHn + col) = v;
                    }
                }
            }
        }
    }
}

// ---------------------------------------------------------------------------
// softmax over NSC=999 (fp16 scores, stride 1024) -> fp16 attn row, eye-shift.
// 256 threads x 4 halves each.
// ---------------------------------------------------------------------------
__global__ __launch_bounds__(256) void k_softmax_attn() {
    int blk = blockIdx.x;
    int b = blk / An;
    int i = blk - b * An;
    const __half* s = g_scoresH + ((long)b * APAD + i) * NPAD;
    __half* arow = g_attnH + ((long)b * APAD + i) * NPAD;
    int tid = threadIdx.x;
    __shared__ float red[8];

    const int c4 = tid * 4;
    __half2 h01 = *reinterpret_cast<const __half2*>(s + c4);
    __half2 h23 = *reinterpret_cast<const __half2*>(s + c4 + 2);
    float vv[4] = { __low2float(h01), __high2float(h01),
                    __low2float(h23), __high2float(h23) };

    float mx = -3.4e38f;
#pragma unroll
    for (int e = 0; e < 4; e++)
        if (c4 + e < NSC) mx = fmaxf(mx, vv[e]);
#pragma unroll
    for (int o = 16; o; o >>= 1) mx = fmaxf(mx, __shfl_xor_sync(0xffffffffu, mx, o));
    if ((tid & 31) == 0) red[tid >> 5] = mx;
    __syncthreads();
    mx = red[0];
#pragma unroll
    for (int w = 1; w < 8; w++) mx = fmaxf(mx, red[w]);
    __syncthreads();

    float ex[4];
    float sum = 0.0f;
#pragma unroll
    for (int e = 0; e < 4; e++) {
        float t = 0.0f;
        if (c4 + e < NSC) { t = __expf(vv[e] - mx); sum += t; }
        ex[e] = t;
    }
#pragma unroll
    for (int o = 16; o; o >>= 1) sum += __shfl_xor_sync(0xffffffffu, sum, o);
    if ((tid & 31) == 0) red[tid >> 5] = sum;
    __syncthreads();
    float tot = red[0];
#pragma unroll
    for (int w = 1; w < 8; w++) tot += red[w];
    float inv = 1.0f / tot;

#pragma unroll
    for (int e = 0; e < 4; e++) {
        int c = c4 + e;
        if (c < NSC) {
            int j = c + (c >= i ? 1 : 0);
            arow[j] = __float2half(ex[e] * inv);
        }
    }
    if (tid == 0) arow[i] = __half(0.0f);
    if (tid >= 250) {                          // zero cols 1000..1023
        int c = 1000 + (tid - 250) * 4;
#pragma unroll
        for (int e = 0; e < 4; e++) arow[c + e] = __half(0.0f);
    }
}

// ---------------------------------------------------------------------------
extern "C" void kernel_launch(void* const* d_in, const int* in_sizes, int n_in,
                              void* d_out, int out_size) {
    const float* fv   = (const float*)d_in[0];
    const int*   z    = (const int*)d_in[1];
    const int*   y    = (const int*)d_in[2];
    const int*   x    = (const int*)d_in[3];
    const int*   inv  = (const int*)d_in[4];
    const float* Wt   = (const float*)d_in[5];
    const float* bias = (const float*)d_in[6];
    float* out = (float*)d_out;

    cudaFuncSetAttribute(k_gemm<true>,  cudaFuncAttributeMaxDynamicSharedMemorySize, SMEM_G);
    cudaFuncSetAttribute(k_gemm<false>, cudaFuncAttributeMaxDynamicSharedMemorySize, SMEM_G);

    k_precomp<<<(An * CHn + 255) / 256, 256>>>(z, y, x, inv);
    k_WT<<<(APAD * CHn + 255) / 256, 256>>>(Wt, bias);
    k_gather<<<dim3(An, Bn), 256>>>(fv);
    k_transpose<<<dim3(APAD / 32, CHn / 32, Bn), dim3(32, 8)>>>();
    k_gemm<true><<<dim3(NPAD / 128, MtotPad / 128), 128, SMEM_G>>>(nullptr);
    k_softmax_attn<<<Bn * An, 256>>>();
    k_gemm<false><<<dim3(CHn / 128, APAD / 128, Bn), 128, SMEM_G>>>(out);
}